// round 1
// baseline (speedup 1.0000x reference)
#include <cuda_runtime.h>
#include <math.h>

// ---------------- problem constants ----------------
#define S_NUM   16
#define O_NUM   15
#define BATCH   4096
#define N_IN    64
#define WSHAPE  3120
#define BSHAPE  41
#define TOTAL_ELEMS (S_NUM * BATCH * O_NUM)   // 983040
#define BTILE   128
#define NBLK_B  (BATCH / BTILE)               // 32
#define NPART   (S_NUM * O_NUM * NBLK_B)      // 7680
#define EPSF    1e-20f
#define TEMP    0.03f

// scratch (allocation-free rule: __device__ globals)
__device__ float g_constw[S_NUM * O_NUM * WSHAPE];   // ~3 MB
__device__ float g_partials[NPART];

// ---------------- phase 1: gumbel-ish gate -> constw ----------------
__global__ void eql_constw(const float* __restrict__ scores,
                           const float* __restrict__ base,
                           const float* __restrict__ u0,
                           const float* __restrict__ u1) {
    int i = blockIdx.x * 256 + threadIdx.x;
    if (i >= S_NUM * O_NUM * WSHAPE) return;
    int ow = i % (O_NUM * WSHAPE);
    float sc    = scores[ow];
    float cs    = 1.0f / (1.0f + expf(-sc));
    float logit = logf(cs + EPSF) - logf(1.0f - cs + EPSF);
    float noise = -logf(logf(u0[i] + EPSF) / logf(u1[i] + EPSF) + EPSF);
    float z     = (logit + noise) * TEMP;
    float soft  = 1.0f / (1.0f + expf(-z));
    float hard  = (soft > 0.5f) ? 1.0f : 0.0f;
    g_constw[i] = base[ow] * ((hard - soft) + soft);
}

// ---------------- ops ----------------
__device__ __forceinline__ float op_mul(float a, float b, float& r) {
    r += fmaxf(-100.0f - a, 0.0f) + fmaxf(a - 100.0f, 0.0f)
       + fmaxf(-100.0f - b, 0.0f) + fmaxf(b - 100.0f, 0.0f);
    return fminf(fmaxf(a, -100.0f), 100.0f) * fminf(fmaxf(b, -100.0f), 100.0f);
}
__device__ __forceinline__ float op_div(float a, float b, float& r) {
    r += fmaxf(0.01f - b, 0.0f);
    return (b < 0.01f) ? 0.0f : (a / b);
}
__device__ __forceinline__ float op_log(float a, float& r) {
    r += fmaxf(0.001f - a, 0.0f);
    return logf(fmaxf(a, 0.001f));
}
__device__ __forceinline__ float op_exp(float a, float& r) {
    r += fmaxf(-10.0f - a, 0.0f) + fmaxf(a - 4.0f, 0.0f);
    return expf(fminf(fmaxf(a, -10.0f), 4.0f));
}

// ---------------- matvec helper ----------------
// hidden[0..63] lives in sobs (transposed obs tile), hidden[64..] in h[].
#define OBS_STRIDE 129

template <int WLO, int INALL, int BLO, int NREG>
__device__ __forceinline__ void layer_matvec(const float* __restrict__ sobs,
                                             const float* __restrict__ ws,
                                             const float* __restrict__ sb,
                                             const float (&h)[30], int t,
                                             float (&acc)[8]) {
    #pragma unroll
    for (int e = 0; e < INALL; e++) acc[e] = sb[BLO + e];
    // obs part (rolled-ish, dynamic shared indexing is fine)
    #pragma unroll 4
    for (int d = 0; d < 64; d++) {
        float hv = sobs[d * OBS_STRIDE + t];
        #pragma unroll
        for (int e = 0; e < INALL; e++)
            acc[e] = fmaf(hv, ws[WLO + d * INALL + e], acc[e]);
    }
    // register-resident hidden tail (fully unrolled, constant indices)
    #pragma unroll
    for (int d = 0; d < NREG; d++) {
        float hv = h[d];
        #pragma unroll
        for (int e = 0; e < INALL; e++)
            acc[e] = fmaf(hv, ws[WLO + (64 + d) * INALL + e], acc[e]);
    }
}

// ---------------- phase 2: main network ----------------
__global__ void __launch_bounds__(BTILE)
eql_main(const float* __restrict__ obs,
         const float* __restrict__ constb,
         float* __restrict__ out) {
    __shared__ float sobs[64 * OBS_STRIDE];  // 33024 B
    __shared__ float ws[WSHAPE];             // 12480 B
    __shared__ float sb[BSHAPE];
    __shared__ float sred[4];

    const int t  = threadIdx.x;
    const int s  = blockIdx.z;
    const int o  = blockIdx.y;
    const int b0 = blockIdx.x * BTILE;

    // load weights for (s,o): 3120 floats, 16B-aligned -> float4
    {
        const float4* wg4 = reinterpret_cast<const float4*>(
            g_constw + (size_t)(s * O_NUM + o) * WSHAPE);
        float4* ws4 = reinterpret_cast<float4*>(ws);
        #pragma unroll
        for (int i = t; i < WSHAPE / 4; i += BTILE) ws4[i] = wg4[i];
    }
    if (t < BSHAPE) sb[t] = constb[o * BSHAPE + t];
    // obs tile, transposed into shared: sobs[col*129 + rowInTile]
    {
        const float* og = obs + (size_t)b0 * N_IN;
        #pragma unroll
        for (int i = t; i < BTILE * N_IN; i += BTILE) {
            int bl = i >> 6, c = i & 63;
            sobs[c * OBS_STRIDE + bl] = og[i];
        }
    }
    __syncthreads();

    float h[30];
    float acc[8];
    float racc = 0.0f;

    // L0: wlo=0, ins=64, inall=6, blo=0, ops mul,mul,mul
    layer_matvec<0, 6, 0, 0>(sobs, ws, sb, h, t, acc);
    h[0] = op_mul(acc[0], acc[1], racc);
    h[1] = op_mul(acc[2], acc[3], racc);
    h[2] = op_mul(acc[4], acc[5], racc);

    // L1: wlo=384, ins=67, inall=6, blo=6, ops div,div,div
    layer_matvec<384, 6, 6, 3>(sobs, ws, sb, h, t, acc);
    h[3] = op_div(acc[0], acc[1], racc);
    h[4] = op_div(acc[2], acc[3], racc);
    h[5] = op_div(acc[4], acc[5], racc);

    // L2: wlo=786, ins=70, inall=8, blo=12, ops log,log,exp,exp,sin,sin,cos,cos
    layer_matvec<786, 8, 12, 6>(sobs, ws, sb, h, t, acc);
    h[6]  = op_log(acc[0], racc);
    h[7]  = op_log(acc[1], racc);
    h[8]  = op_exp(acc[2], racc);
    h[9]  = op_exp(acc[3], racc);
    h[10] = sinf(acc[4]);
    h[11] = sinf(acc[5]);
    h[12] = cosf(acc[6]);
    h[13] = cosf(acc[7]);

    // L3: wlo=1346, ins=78, inall=8, blo=20
    layer_matvec<1346, 8, 20, 14>(sobs, ws, sb, h, t, acc);
    h[14] = op_log(acc[0], racc);
    h[15] = op_log(acc[1], racc);
    h[16] = op_exp(acc[2], racc);
    h[17] = op_exp(acc[3], racc);
    h[18] = sinf(acc[4]);
    h[19] = sinf(acc[5]);
    h[20] = cosf(acc[6]);
    h[21] = cosf(acc[7]);

    // L4: wlo=1970, ins=86, inall=6, blo=28, ops mul,div,log,exp
    layer_matvec<1970, 6, 28, 22>(sobs, ws, sb, h, t, acc);
    h[22] = op_mul(acc[0], acc[1], racc);
    h[23] = op_div(acc[2], acc[3], racc);
    h[24] = op_log(acc[4], racc);
    h[25] = op_exp(acc[5], racc);

    // L5: wlo=2486, ins=90, inall=6, blo=34
    layer_matvec<2486, 6, 34, 26>(sobs, ws, sb, h, t, acc);
    h[26] = op_mul(acc[0], acc[1], racc);
    h[27] = op_div(acc[2], acc[3], racc);
    h[28] = op_log(acc[4], racc);
    h[29] = op_exp(acc[5], racc);

    // final head: wlo=3026, ins=94, inall=1, blo=40
    float last = sb[40];
    #pragma unroll 4
    for (int d = 0; d < 64; d++)
        last = fmaf(sobs[d * OBS_STRIDE + t], ws[3026 + d], last);
    #pragma unroll
    for (int d = 0; d < 30; d++)
        last = fmaf(h[d], ws[3026 + 64 + d], last);

    const int b = b0 + t;
    out[((size_t)(s * BATCH + b)) * O_NUM + o] = last;

    // regu block reduction (deterministic: shuffle tree + fixed 4-way sum)
    #pragma unroll
    for (int off = 16; off > 0; off >>= 1)
        racc += __shfl_down_sync(0xFFFFFFFFu, racc, off);
    if ((t & 31) == 0) sred[t >> 5] = racc;
    __syncthreads();
    if (t == 0) {
        float p = (sred[0] + sred[1]) + (sred[2] + sred[3]);
        g_partials[(s * O_NUM + o) * NBLK_B + blockIdx.x] = p;
    }
}

// ---------------- phase 3: regu final reduce ----------------
__global__ void eql_reduce(float* __restrict__ out) {
    __shared__ double sd[256];
    double acc = 0.0;
    for (int i = threadIdx.x; i < NPART; i += 256) acc += (double)g_partials[i];
    sd[threadIdx.x] = acc;
    __syncthreads();
    for (int k = 128; k > 0; k >>= 1) {
        if (threadIdx.x < k) sd[threadIdx.x] += sd[threadIdx.x + k];
        __syncthreads();
    }
    if (threadIdx.x == 0)
        out[TOTAL_ELEMS] = (float)(sd[0] / (double)TOTAL_ELEMS);
}

// ---------------- launch ----------------
extern "C" void kernel_launch(void* const* d_in, const int* in_sizes, int n_in,
                              void* d_out, int out_size) {
    const float* obs    = (const float*)d_in[0];   // (4096, 64)
    const float* scores = (const float*)d_in[1];   // (15, 3120)
    const float* cwbase = (const float*)d_in[2];   // (15, 3120)
    const float* constb = (const float*)d_in[3];   // (15, 41)
    const float* u0     = (const float*)d_in[4];   // (16, 15, 3120)
    const float* u1     = (const float*)d_in[5];   // (16, 15, 3120)
    float* out = (float*)d_out;                    // 983040 outs + 1 regu

    int ntot = S_NUM * O_NUM * WSHAPE;             // 748800
    eql_constw<<<(ntot + 255) / 256, 256>>>(scores, cwbase, u0, u1);

    dim3 grid(NBLK_B, O_NUM, S_NUM);               // (32, 15, 16)
    eql_main<<<grid, BTILE>>>(obs, constb, out);

    eql_reduce<<<1, 256>>>(out);
}

// round 2
// speedup vs baseline: 1.0733x; 1.0733x over previous
#include <cuda_runtime.h>
#include <math.h>

// ---------------- problem constants ----------------
#define S_NUM   16
#define O_NUM   15
#define BATCH   4096
#define N_IN    64
#define WSHAPE  3120
#define BSHAPE  41
#define TOTAL_ELEMS (S_NUM * BATCH * O_NUM)   // 983040
#define BTILE   256                           // batch per block (2 per thread)
#define NTHR    128
#define NBLK_B  (BATCH / BTILE)               // 16
#define NPART   (S_NUM * O_NUM * NBLK_B)      // 3840
#define EPSF    1e-20f
#define TEMP    0.03f

typedef unsigned long long u64;

// scratch (allocation-free rule: __device__ globals)
__device__ float g_constw[S_NUM * O_NUM * WSHAPE];   // ~3 MB
__device__ float g_partials[NPART];

// ---------------- packed f32x2 helpers ----------------
__device__ __forceinline__ u64 pk(float lo, float hi) {
    u64 r; asm("mov.b64 %0, {%1, %2};" : "=l"(r) : "f"(lo), "f"(hi)); return r;
}
__device__ __forceinline__ float2 unpk(u64 v) {
    float2 f; asm("mov.b64 {%0, %1}, %2;" : "=f"(f.x), "=f"(f.y) : "l"(v)); return f;
}
__device__ __forceinline__ u64 dup2(float x) { return pk(x, x); }
__device__ __forceinline__ u64 ffma2(u64 a, u64 b, u64 c) {
    u64 d; asm("fma.rn.f32x2 %0, %1, %2, %3;" : "=l"(d) : "l"(a), "l"(b), "l"(c));
    return d;
}

// ---------------- phase 1: gumbel-ish gate -> constw ----------------
__global__ void eql_constw(const float* __restrict__ scores,
                           const float* __restrict__ base,
                           const float* __restrict__ u0,
                           const float* __restrict__ u1) {
    int i = blockIdx.x * 256 + threadIdx.x;
    if (i >= S_NUM * O_NUM * WSHAPE) return;
    int ow = i % (O_NUM * WSHAPE);
    float sc    = scores[ow];
    float cs    = 1.0f / (1.0f + expf(-sc));
    float logit = logf(cs + EPSF) - logf(1.0f - cs + EPSF);
    float noise = -logf(logf(u0[i] + EPSF) / logf(u1[i] + EPSF) + EPSF);
    float z     = (logit + noise) * TEMP;
    float soft  = 1.0f / (1.0f + expf(-z));
    float hard  = (soft > 0.5f) ? 1.0f : 0.0f;
    g_constw[i] = base[ow] * ((hard - soft) + soft);
}

// ---------------- scalar ops (applied per packed lane) ----------------
__device__ __forceinline__ float op_mul(float a, float b, float& r) {
    r += fmaxf(-100.0f - a, 0.0f) + fmaxf(a - 100.0f, 0.0f)
       + fmaxf(-100.0f - b, 0.0f) + fmaxf(b - 100.0f, 0.0f);
    return fminf(fmaxf(a, -100.0f), 100.0f) * fminf(fmaxf(b, -100.0f), 100.0f);
}
__device__ __forceinline__ float op_div(float a, float b, float& r) {
    r += fmaxf(0.01f - b, 0.0f);
    return (b < 0.01f) ? 0.0f : (a / b);
}
__device__ __forceinline__ float op_log(float a, float& r) {
    r += fmaxf(0.001f - a, 0.0f);
    return logf(fmaxf(a, 0.001f));
}
__device__ __forceinline__ float op_exp(float a, float& r) {
    r += fmaxf(-10.0f - a, 0.0f) + fmaxf(a - 4.0f, 0.0f);
    return expf(fminf(fmaxf(a, -10.0f), 4.0f));
}

__device__ __forceinline__ u64 opk_mul(u64 A, u64 B, float& r) {
    float2 a = unpk(A), b = unpk(B);
    return pk(op_mul(a.x, b.x, r), op_mul(a.y, b.y, r));
}
__device__ __forceinline__ u64 opk_div(u64 A, u64 B, float& r) {
    float2 a = unpk(A), b = unpk(B);
    return pk(op_div(a.x, b.x, r), op_div(a.y, b.y, r));
}
__device__ __forceinline__ u64 opk_log(u64 A, float& r) {
    float2 a = unpk(A);
    return pk(op_log(a.x, r), op_log(a.y, r));
}
__device__ __forceinline__ u64 opk_exp(u64 A, float& r) {
    float2 a = unpk(A);
    return pk(op_exp(a.x, r), op_exp(a.y, r));
}
__device__ __forceinline__ u64 opk_sin(u64 A) {
    float2 a = unpk(A); return pk(sinf(a.x), sinf(a.y));
}
__device__ __forceinline__ u64 opk_cos(u64 A) {
    float2 a = unpk(A); return pk(cosf(a.x), cosf(a.y));
}

// ---------------- packed matvec ----------------
// hidden[0..63] (obs) lives in sobs2 (packed batch-pair tile), rest in h[].
#define OBS2_STRIDE 129   // u64 elements per input-dim row (pad vs 128)

template <int WLO, int INALL, int BLO, int NREG>
__device__ __forceinline__ void layer_matvec(const u64* __restrict__ sobs2,
                                             const u64* __restrict__ ws2,
                                             const float* __restrict__ sb,
                                             const u64 (&h)[30], int t,
                                             u64 (&acc)[8]) {
    #pragma unroll
    for (int e = 0; e < INALL; e++) acc[e] = dup2(sb[BLO + e]);
    // obs part: 64 dims from shared; weights as LDS.128 (2 duplicated weights)
    #pragma unroll 8
    for (int d = 0; d < 64; d++) {
        u64 hv = sobs2[d * OBS2_STRIDE + t];
        const ulonglong2* wp =
            reinterpret_cast<const ulonglong2*>(ws2 + WLO + d * INALL);
        #pragma unroll
        for (int e2 = 0; e2 < INALL / 2; e2++) {
            ulonglong2 w = wp[e2];
            acc[2 * e2]     = ffma2(hv, w.x, acc[2 * e2]);
            acc[2 * e2 + 1] = ffma2(hv, w.y, acc[2 * e2 + 1]);
        }
    }
    // register-resident hidden tail (must fully unroll: h index constant)
    #pragma unroll
    for (int d = 0; d < NREG; d++) {
        u64 hv = h[d];
        const ulonglong2* wp =
            reinterpret_cast<const ulonglong2*>(ws2 + WLO + (64 + d) * INALL);
        #pragma unroll
        for (int e2 = 0; e2 < INALL / 2; e2++) {
            ulonglong2 w = wp[e2];
            acc[2 * e2]     = ffma2(hv, w.x, acc[2 * e2]);
            acc[2 * e2 + 1] = ffma2(hv, w.y, acc[2 * e2 + 1]);
        }
    }
}

// dynamic shared layout (bytes):
//   sobs2 : 64 * 129 u64              = 66048
//   ws2   : 3120 u64 (dup weights)    = 24960
//   sb    : 41 f32 + sred 4 f32       = 180
#define SMEM_SOBS_U64   (64 * OBS2_STRIDE)
#define SMEM_BYTES      (SMEM_SOBS_U64 * 8 + WSHAPE * 8 + 48 * 4)

// ---------------- phase 2: main network ----------------
__global__ void __launch_bounds__(NTHR)
eql_main(const float* __restrict__ obs,
         const float* __restrict__ constb,
         float* __restrict__ out) {
    extern __shared__ __align__(16) unsigned char smem_raw[];
    u64*   sobs2 = reinterpret_cast<u64*>(smem_raw);
    u64*   ws2   = sobs2 + SMEM_SOBS_U64;
    float* sb    = reinterpret_cast<float*>(ws2 + WSHAPE);
    float* sred  = sb + 44;

    const int t  = threadIdx.x;
    const int s  = blockIdx.z;
    const int o  = blockIdx.y;
    const int b0 = blockIdx.x * BTILE;

    // weights for (s,o), duplicated into both f32x2 lanes
    {
        const float* wg = g_constw + (size_t)(s * O_NUM + o) * WSHAPE;
        float2* ws2f = reinterpret_cast<float2*>(ws2);
        #pragma unroll
        for (int i = t; i < WSHAPE; i += NTHR) {
            float w = wg[i];
            ws2f[i] = make_float2(w, w);
        }
    }
    if (t < BSHAPE) sb[t] = constb[o * BSHAPE + t];
    // obs tile transposed into packed batch-pairs:
    // sobs2[d*129 + p] = {obs[b0+2p][d], obs[b0+2p+1][d]}
    {
        float* sobsf = reinterpret_cast<float*>(sobs2);
        const float* og = obs + (size_t)b0 * N_IN;
        #pragma unroll
        for (int i = t; i < BTILE * N_IN; i += NTHR) {
            int b = i >> 6, d = i & 63;
            sobsf[d * (2 * OBS2_STRIDE) + b] = og[i];
        }
    }
    __syncthreads();

    u64 h[30];
    u64 acc[8];
    float racc = 0.0f;

    // L0: wlo=0, inall=6, blo=0, ops mul,mul,mul
    layer_matvec<0, 6, 0, 0>(sobs2, ws2, sb, h, t, acc);
    h[0] = opk_mul(acc[0], acc[1], racc);
    h[1] = opk_mul(acc[2], acc[3], racc);
    h[2] = opk_mul(acc[4], acc[5], racc);

    // L1: wlo=384, inall=6, blo=6, ops div,div,div
    layer_matvec<384, 6, 6, 3>(sobs2, ws2, sb, h, t, acc);
    h[3] = opk_div(acc[0], acc[1], racc);
    h[4] = opk_div(acc[2], acc[3], racc);
    h[5] = opk_div(acc[4], acc[5], racc);

    // L2: wlo=786, inall=8, blo=12, ops log,log,exp,exp,sin,sin,cos,cos
    layer_matvec<786, 8, 12, 6>(sobs2, ws2, sb, h, t, acc);
    h[6]  = opk_log(acc[0], racc);
    h[7]  = opk_log(acc[1], racc);
    h[8]  = opk_exp(acc[2], racc);
    h[9]  = opk_exp(acc[3], racc);
    h[10] = opk_sin(acc[4]);
    h[11] = opk_sin(acc[5]);
    h[12] = opk_cos(acc[6]);
    h[13] = opk_cos(acc[7]);

    // L3: wlo=1346, inall=8, blo=20
    layer_matvec<1346, 8, 20, 14>(sobs2, ws2, sb, h, t, acc);
    h[14] = opk_log(acc[0], racc);
    h[15] = opk_log(acc[1], racc);
    h[16] = opk_exp(acc[2], racc);
    h[17] = opk_exp(acc[3], racc);
    h[18] = opk_sin(acc[4]);
    h[19] = opk_sin(acc[5]);
    h[20] = opk_cos(acc[6]);
    h[21] = opk_cos(acc[7]);

    // L4: wlo=1970, inall=6, blo=28, ops mul,div,log,exp
    layer_matvec<1970, 6, 28, 22>(sobs2, ws2, sb, h, t, acc);
    h[22] = opk_mul(acc[0], acc[1], racc);
    h[23] = opk_div(acc[2], acc[3], racc);
    h[24] = opk_log(acc[4], racc);
    h[25] = opk_exp(acc[5], racc);

    // L5: wlo=2486, inall=6, blo=34
    layer_matvec<2486, 6, 34, 26>(sobs2, ws2, sb, h, t, acc);
    h[26] = opk_mul(acc[0], acc[1], racc);
    h[27] = opk_div(acc[2], acc[3], racc);
    h[28] = opk_log(acc[4], racc);
    h[29] = opk_exp(acc[5], racc);

    // final head: wlo=3026, inall=1, blo=40
    u64 last = dup2(sb[40]);
    #pragma unroll 8
    for (int d = 0; d < 64; d++)
        last = ffma2(sobs2[d * OBS2_STRIDE + t], ws2[3026 + d], last);
    #pragma unroll
    for (int d = 0; d < 30; d++)
        last = ffma2(h[d], ws2[3026 + 64 + d], last);

    float2 lv = unpk(last);
    const int b = b0 + 2 * t;
    out[((size_t)(s * BATCH + b))     * O_NUM + o] = lv.x;
    out[((size_t)(s * BATCH + b + 1)) * O_NUM + o] = lv.y;

    // regu block reduction (deterministic)
    #pragma unroll
    for (int off = 16; off > 0; off >>= 1)
        racc += __shfl_down_sync(0xFFFFFFFFu, racc, off);
    if ((t & 31) == 0) sred[t >> 5] = racc;
    __syncthreads();
    if (t == 0) {
        float p = (sred[0] + sred[1]) + (sred[2] + sred[3]);
        g_partials[(s * O_NUM + o) * NBLK_B + blockIdx.x] = p;
    }
}

// ---------------- phase 3: regu final reduce ----------------
__global__ void eql_reduce(float* __restrict__ out) {
    __shared__ double sd[256];
    double acc = 0.0;
    for (int i = threadIdx.x; i < NPART; i += 256) acc += (double)g_partials[i];
    sd[threadIdx.x] = acc;
    __syncthreads();
    for (int k = 128; k > 0; k >>= 1) {
        if (threadIdx.x < k) sd[threadIdx.x] += sd[threadIdx.x + k];
        __syncthreads();
    }
    if (threadIdx.x == 0)
        out[TOTAL_ELEMS] = (float)(sd[0] / (double)TOTAL_ELEMS);
}

// ---------------- launch ----------------
extern "C" void kernel_launch(void* const* d_in, const int* in_sizes, int n_in,
                              void* d_out, int out_size) {
    const float* obs    = (const float*)d_in[0];   // (4096, 64)
    const float* scores = (const float*)d_in[1];   // (15, 3120)
    const float* cwbase = (const float*)d_in[2];   // (15, 3120)
    const float* constb = (const float*)d_in[3];   // (15, 41)
    const float* u0     = (const float*)d_in[4];   // (16, 15, 3120)
    const float* u1     = (const float*)d_in[5];   // (16, 15, 3120)
    float* out = (float*)d_out;                    // 983040 outs + 1 regu

    cudaFuncSetAttribute(eql_main, cudaFuncAttributeMaxDynamicSharedMemorySize,
                         SMEM_BYTES);

    int ntot = S_NUM * O_NUM * WSHAPE;             // 748800
    eql_constw<<<(ntot + 255) / 256, 256>>>(scores, cwbase, u0, u1);

    dim3 grid(NBLK_B, O_NUM, S_NUM);               // (16, 15, 16)
    eql_main<<<grid, NTHR, SMEM_BYTES>>>(obs, constb, out);

    eql_reduce<<<1, 256>>>(out);
}